// round 8
// baseline (speedup 1.0000x reference)
#include <cuda_runtime.h>
#include <cuda_bf16.h>
#include <cstdint>

#define MATSZ (512*512*4)

__device__ __align__(16) float g_X0 [8192*512];
__device__ __align__(16) float g_ZXe[128*2048*64];
__device__ __align__(16) float g_ZXd[128*2048*64];
__device__ __align__(16) float g_H1 [(size_t)8192*2048];
__device__ __align__(16) float g_dout[8192*512];
__device__ __align__(16) float g_WR [(size_t)10*MATSZ];
__device__ __align__(16) float g_h[2][3*512*64];
__device__ int g_idx_in[8192];
__device__ int g_idx_tg[8192];
__device__ unsigned g_count = 0;
__device__ unsigned g_gen = 0;

__device__ __forceinline__ unsigned long long pack2(float lo, float hi){
    unsigned long long r;
    asm("mov.b64 %0,{%1,%2};":"=l"(r):"r"(__float_as_uint(lo)),"r"(__float_as_uint(hi)));
    return r;
}
__device__ __forceinline__ void fma2(unsigned long long&d,unsigned long long a,unsigned long long b){
    asm("fma.rn.f32x2 %0,%1,%2,%0;":"+l"(d):"l"(a),"l"(b));
}
__device__ __forceinline__ float2 unpack2(unsigned long long v){
    unsigned lo,hi; asm("mov.b64 {%0,%1},%2;":"=r"(lo),"=r"(hi):"l"(v));
    return make_float2(__uint_as_float(lo),__uint_as_float(hi));
}
__device__ __forceinline__ float sigm(float x){ return __fdividef(1.f,1.f+__expf(-x)); }

// ---- prep: dtype sniff (int32 vs int64) + gather build: r = t*64+b ----
__global__ void prep_k(const int* __restrict__ in, const int* __restrict__ tg){
    __shared__ int nz[2];
    int tid = threadIdx.x;
    if(tid<2) nz[tid]=0;
    __syncthreads();
    int a=0,b=0;
    for(int i=tid;i<4096;i+=256){ if(in[2*i+1]) a=1; if(tg[2*i+1]) b=1; }
    if(a) atomicOr(&nz[0],1);
    if(b) atomicOr(&nz[1],1);
    __syncthreads();
    bool in64 = (nz[0]==0), tg64 = (nz[1]==0);
    for(int r=tid;r<8192;r+=256){
        int bb=r&63, t=r>>6, p=bb*128+t;
        g_idx_in[r] = in64 ? in[2*p] : in[p];
        g_idx_tg[r] = tg64 ? tg[2*p] : tg[p];
    }
}

// ---- weight reorder: g_WR[m][k][u][g] = src_m[k][g*512+u] ----
// m: 0-2 encWh l0-2, 3-4 encWx l1-2, 5-7 decWh, 8-9 decWx
__global__ void reorder_k(const float* __restrict__ eWh,const float* __restrict__ eWx,
                          const float* __restrict__ dWh,const float* __restrict__ dWx){
    const int total = 10*512*2048;
    for(int s=blockIdx.x*blockDim.x+threadIdx.x; s<total; s+=gridDim.x*blockDim.x){
        int m = s/(512*2048);
        int rem = s - m*(512*2048);            // k*2048 + g*512 + u
        int u = rem&511, g=(rem>>9)&3, k=rem>>11;
        const float* src; int l;
        if(m<3){src=eWh;l=m;} else if(m<5){src=eWx;l=m-2;}
        else if(m<8){src=dWh;l=m-5;} else {src=dWx;l=m-7;}
        g_WR[((size_t)(m*512+k)*512+u)*4+g] = src[(size_t)l*512*2048+rem];
    }
}

// ---- generic SGEMM: C = op(gather(A)@B + bias), 128x128x16 tiles ----
// cmode 0: C[r*N+c]; 1: C[(r>>6)*131072 + c*64 + (r&63)]; 2: C[((r&63)*128+(r>>6))*8192+c]
__global__ void __launch_bounds__(256) sgemm_k(
    const float* __restrict__ A,const float* __restrict__ Bm,
    const float* __restrict__ bias,float* __restrict__ C,
    int M,int N,int K,const int* __restrict__ gather,int cmode,int dorelu)
{
    __shared__ float As[16][132];
    __shared__ float Bs[16][128];
    const int tid=threadIdx.x, tx=tid&15, ty=tid>>4;
    const int m0=blockIdx.y<<7, n0=blockIdx.x<<7;
    const float* aptr[2]; int arow[2],akq[2];
    #pragma unroll
    for(int i=0;i<2;i++){
        int L=tid+i*256, row=L>>2, kq=L&3;
        arow[i]=row; akq[i]=kq;
        int gr=m0+row, src = gather ? gather[gr] : gr;
        aptr[i] = A + (size_t)src*K + kq*4;
    }
    const float* bptr[2]; int bkrow[2],bcol[2];
    #pragma unroll
    for(int i=0;i<2;i++){
        int L=tid+i*256, krow=L>>5, col4=(L&31)*4;
        bkrow[i]=krow; bcol[i]=col4;
        bptr[i] = Bm + (size_t)krow*N + n0 + col4;
    }
    unsigned long long acc[8][4];
    #pragma unroll
    for(int i=0;i<8;i++)
        #pragma unroll
        for(int j=0;j<4;j++) acc[i][j]=0ull;

    for(int k0=0;k0<K;k0+=16){
        float4 av[2],bv[2];
        #pragma unroll
        for(int i=0;i<2;i++) av[i]=*(const float4*)(aptr[i]+k0);
        #pragma unroll
        for(int i=0;i<2;i++) bv[i]=*(const float4*)(bptr[i]+(size_t)k0*N);
        __syncthreads();
        #pragma unroll
        for(int i=0;i<2;i++){
            As[akq[i]*4+0][arow[i]]=av[i].x;
            As[akq[i]*4+1][arow[i]]=av[i].y;
            As[akq[i]*4+2][arow[i]]=av[i].z;
            As[akq[i]*4+3][arow[i]]=av[i].w;
            *(float4*)&Bs[bkrow[i]][bcol[i]]=bv[i];
        }
        __syncthreads();
        #pragma unroll
        for(int kk=0;kk<16;kk++){
            float4 a0=*(const float4*)&As[kk][ty*8];
            float4 a1=*(const float4*)&As[kk][ty*8+4];
            ulonglong2 b0=*(const ulonglong2*)&Bs[kk][tx*8];
            ulonglong2 b1=*(const ulonglong2*)&Bs[kk][tx*8+4];
            float aa[8]={a0.x,a0.y,a0.z,a0.w,a1.x,a1.y,a1.z,a1.w};
            #pragma unroll
            for(int i=0;i<8;i++){
                unsigned long long ai=pack2(aa[i],aa[i]);
                fma2(acc[i][0],ai,b0.x); fma2(acc[i][1],ai,b0.y);
                fma2(acc[i][2],ai,b1.x); fma2(acc[i][3],ai,b1.y);
            }
        }
    }
    const int cbase=n0+tx*8;
    float bv8[8];
    #pragma unroll
    for(int j=0;j<8;j++) bv8[j] = bias ? __ldg(&bias[cbase+j]) : 0.f;
    #pragma unroll
    for(int i=0;i<8;i++){
        int r=m0+ty*8+i;
        float v[8];
        #pragma unroll
        for(int j=0;j<4;j++){ float2 f=unpack2(acc[i][j]); v[2*j]=f.x; v[2*j+1]=f.y; }
        #pragma unroll
        for(int j=0;j<8;j++){ v[j]+=bv8[j]; if(dorelu) v[j]=fmaxf(v[j],0.f); }
        if(cmode==0){
            float4* p=(float4*)&C[(size_t)r*N+cbase];
            p[0]=make_float4(v[0],v[1],v[2],v[3]);
            p[1]=make_float4(v[4],v[5],v[6],v[7]);
        } else if(cmode==1){
            size_t base=(size_t)(r>>6)*131072 + (r&63);
            #pragma unroll
            for(int j=0;j<8;j++) C[base+(size_t)(cbase+j)*64]=v[j];
        } else {
            size_t base=(size_t)((r&63)*128+(r>>6))*8192 + cbase;
            float4* p=(float4*)&C[base];
            p[0]=make_float4(v[0],v[1],v[2],v[3]);
            p[1]=make_float4(v[4],v[5],v[6],v[7]);
        }
    }
}

// ---- software grid barrier ----
__device__ __forceinline__ void gbar(int ncta){
    __syncthreads();
    if(threadIdx.x==0){
        volatile unsigned* genp=&g_gen;
        unsigned my=*genp;
        __threadfence();
        unsigned old=atomicAdd(&g_count,1u);
        if(old==(unsigned)(ncta-1)){
            g_count=0;
            __threadfence();
            g_gen=my+1;
        } else {
            while(*genp==my){ __nanosleep(64); }
        }
    }
    __syncthreads();
}

// ---- persistent recurrence: 256 steps x 3 layers ----
// 128 CTAs x 128 thr. CTA=(b-half of 32)x(8 units); thread owns 2 cells.
__global__ void __launch_bounds__(128) recurrent_k(
    const float* __restrict__ enc_b,const float* __restrict__ dec_b)
{
    __shared__ float sHr[128][32];
    __shared__ float sHw[128][32];
    const int tid=threadIdx.x, la=tid&31, w=tid>>5;
    const int cta=blockIdx.x, b0=(cta&1)<<5, ug=cta>>1;
    const int b=b0+la, u0=ug*8+w*2;
    const int NB=gridDim.x;
    #pragma unroll
    for(int l=0;l<3;l++){
        g_h[0][(l*512+u0)*64+b]=0.f;
        g_h[0][(l*512+u0+1)*64+b]=0.f;
    }
    float cst[3][2]={{0,0},{0,0},{0,0}};
    gbar(NB);

    for(int t=0;t<256;t++){
        const bool enc=(t<128);
        const float* ZX = enc ? g_ZXe+(size_t)t*131072 : g_ZXd+(size_t)(t-128)*131072;
        const float* Wb = enc ? g_WR : g_WR+(size_t)5*MATSZ;
        const float* bia= enc ? enc_b : dec_b;
        const int cur=t&1, nxt=cur^1;
        for(int l=0;l<3;l++){
            float a4[2][4];
            #pragma unroll
            for(int cc=0;cc<2;cc++)
                #pragma unroll
                for(int g=0;g<4;g++){
                    float x=__ldg(&bia[l*2048+g*512+u0+cc]);
                    if(l==0) x += ZX[(g*512+u0+cc)*64+b];
                    a4[cc][g]=x;
                }
            unsigned long long ac[2][2];
            #pragma unroll
            for(int cc=0;cc<2;cc++){
                ac[cc][0]=pack2(a4[cc][0],a4[cc][1]);
                ac[cc][1]=pack2(a4[cc][2],a4[cc][3]);
            }
            const float* Wh = Wb+(size_t)l*MATSZ;
            const float* hr = &g_h[cur][l*32768];
            const float* hx = (l>0)? &g_h[nxt][(l-1)*32768] : nullptr;
            for(int k0=0;k0<512;k0+=128){
                __syncthreads();
                #pragma unroll
                for(int i=0;i<8;i++){
                    int L=tid+i*128, kk=L>>3, c4=(L&7)<<2;
                    *(float4*)&sHr[kk][c4]=__ldcg((const float4*)&hr[(k0+kk)*64+b0+c4]);
                    if(l>0)
                        *(float4*)&sHw[kk][c4]=__ldcg((const float4*)&hx[(k0+kk)*64+b0+c4]);
                }
                __syncthreads();
                if(l==0){
                    #pragma unroll 4
                    for(int kk=0;kk<128;kk++){
                        unsigned long long hh=pack2(sHr[kk][la],sHr[kk][la]);
                        size_t wo=((size_t)(k0+kk)*512+u0)*4;
                        ulonglong2 w0=*(const ulonglong2*)&Wh[wo];
                        ulonglong2 w1=*(const ulonglong2*)&Wh[wo+4];
                        fma2(ac[0][0],hh,w0.x); fma2(ac[0][1],hh,w0.y);
                        fma2(ac[1][0],hh,w1.x); fma2(ac[1][1],hh,w1.y);
                    }
                } else {
                    const float* Wx = Wb+(size_t)(2+l)*MATSZ;
                    #pragma unroll 2
                    for(int kk=0;kk<128;kk++){
                        unsigned long long hh=pack2(sHr[kk][la],sHr[kk][la]);
                        unsigned long long xx=pack2(sHw[kk][la],sHw[kk][la]);
                        size_t wo=((size_t)(k0+kk)*512+u0)*4;
                        ulonglong2 w0=*(const ulonglong2*)&Wh[wo];
                        ulonglong2 w1=*(const ulonglong2*)&Wh[wo+4];
                        ulonglong2 x0=*(const ulonglong2*)&Wx[wo];
                        ulonglong2 x1=*(const ulonglong2*)&Wx[wo+4];
                        fma2(ac[0][0],hh,w0.x); fma2(ac[0][1],hh,w0.y);
                        fma2(ac[1][0],hh,w1.x); fma2(ac[1][1],hh,w1.y);
                        fma2(ac[0][0],xx,x0.x); fma2(ac[0][1],xx,x0.y);
                        fma2(ac[1][0],xx,x1.x); fma2(ac[1][1],xx,x1.y);
                    }
                }
            }
            #pragma unroll
            for(int cc=0;cc<2;cc++){
                float2 g01=unpack2(ac[cc][0]);
                float2 g23=unpack2(ac[cc][1]);
                float ig=sigm(g01.x), fg=sigm(g01.y);
                float gg=tanhf(g23.x), og=sigm(g23.y);
                float cn=fg*cst[l][cc]+ig*gg;
                cst[l][cc]=cn;
                float hn=og*tanhf(cn);
                g_h[nxt][(l*512+u0+cc)*64+b]=hn;
                if(l==2 && !enc)
                    g_dout[(size_t)((t-128)*64+b)*512+u0+cc]=hn;
            }
            gbar(NB);
        }
    }
}

extern "C" void kernel_launch(void* const* d_in, const int* in_sizes, int n_in,
                              void* d_out, int out_size){
    const int*   inputs      =(const int*)  d_in[0];
    const int*   targets     =(const int*)  d_in[1];
    const float* input_embed =(const float*)d_in[2];
    const float* enc_Wd      =(const float*)d_in[3];
    const float* enc_bd      =(const float*)d_in[4];
    const float* enc_Wx      =(const float*)d_in[5];
    const float* enc_Wh      =(const float*)d_in[6];
    const float* enc_b       =(const float*)d_in[7];
    const float* dec_embed   =(const float*)d_in[8];
    const float* dec_Wd      =(const float*)d_in[9];
    const float* dec_bd      =(const float*)d_in[10];
    const float* dec_Wx      =(const float*)d_in[11];
    const float* dec_Wh      =(const float*)d_in[12];
    const float* dec_b       =(const float*)d_in[13];
    const float* out_W1      =(const float*)d_in[14];
    const float* out_b1      =(const float*)d_in[15];
    const float* out_W2      =(const float*)d_in[16];
    const float* out_b2      =(const float*)d_in[17];
    float* out=(float*)d_out;

    float *pX0,*pZXe,*pZXd,*pH1,*pDO;
    int *pIin,*pItg;
    cudaGetSymbolAddress((void**)&pX0, g_X0);
    cudaGetSymbolAddress((void**)&pZXe,g_ZXe);
    cudaGetSymbolAddress((void**)&pZXd,g_ZXd);
    cudaGetSymbolAddress((void**)&pH1, g_H1);
    cudaGetSymbolAddress((void**)&pDO, g_dout);
    cudaGetSymbolAddress((void**)&pIin,g_idx_in);
    cudaGetSymbolAddress((void**)&pItg,g_idx_tg);

    prep_k<<<1,256>>>(inputs,targets);
    reorder_k<<<2048,256>>>(enc_Wh,enc_Wx,dec_Wh,dec_Wx);
    // enc: X0 = relu(gather(embed) @ enc_Wd + enc_bd)
    sgemm_k<<<dim3(4,64),256>>>(input_embed,enc_Wd,enc_bd,pX0,8192,512,64,pIin,0,1);
    // enc: ZXe = X0 @ enc_Wx[0]   (layout [t][col][b])
    sgemm_k<<<dim3(16,64),256>>>(pX0,enc_Wx,nullptr,pZXe,8192,2048,512,nullptr,1,0);
    // dec: X0 = relu(gather(dec_embed) @ dec_Wd + dec_bd)
    sgemm_k<<<dim3(4,64),256>>>(dec_embed,dec_Wd,dec_bd,pX0,8192,512,2048,pItg,0,1);
    // dec: ZXd = X0 @ dec_Wx[0]
    sgemm_k<<<dim3(16,64),256>>>(pX0,dec_Wx,nullptr,pZXd,8192,2048,512,nullptr,1,0);
    // recurrence (enc 128 + dec 128 steps)
    recurrent_k<<<128,128>>>(enc_b,dec_b);
    // head: H1 = relu(dout @ out_W1 + out_b1)
    sgemm_k<<<dim3(16,64),256>>>(pDO,out_W1,out_b1,pH1,8192,2048,512,nullptr,0,1);
    // head: out = relu(H1 @ out_W2 + out_b2), remapped to [B][T][P]
    sgemm_k<<<dim3(64,64),256>>>(pH1,out_W2,out_b2,out,8192,8192,2048,nullptr,2,1);
}

// round 12
// speedup vs baseline: 4.0467x; 4.0467x over previous
#include <cuda_runtime.h>
#include <cuda_bf16.h>
#include <cstdint>

#define MATSZ (512*512*4)

__device__ __align__(16) float g_X0 [8192*512];
__device__ __align__(16) float g_ZXe[128*2048*64];
__device__ __align__(16) float g_ZXd[128*2048*64];
__device__ __align__(16) float g_H1 [(size_t)8192*2048];
__device__ __align__(16) float g_dout[8192*512];
__device__ __align__(16) float g_WR [(size_t)10*MATSZ];   // [m][cta128][k512][uu4][g4]
__device__ __align__(16) float g_h[2][3*512*64];
__device__ int g_idx_in[8192];
__device__ int g_idx_tg[8192];
__device__ unsigned g_count = 0;
__device__ volatile unsigned g_gen = 0;

__device__ __forceinline__ unsigned long long pack2(float lo, float hi){
    unsigned long long r;
    asm("mov.b64 %0,{%1,%2};":"=l"(r):"r"(__float_as_uint(lo)),"r"(__float_as_uint(hi)));
    return r;
}
__device__ __forceinline__ void fma2(unsigned long long&d,unsigned long long a,unsigned long long b){
    asm("fma.rn.f32x2 %0,%1,%2,%0;":"+l"(d):"l"(a),"l"(b));
}
__device__ __forceinline__ float2 unpack2(unsigned long long v){
    unsigned lo,hi; asm("mov.b64 {%0,%1},%2;":"=r"(lo),"=r"(hi):"l"(v));
    return make_float2(__uint_as_float(lo),__uint_as_float(hi));
}
__device__ __forceinline__ float sigm(float x){ return __fdividef(1.f,1.f+__expf(-x)); }

// ---- prep: dtype sniff (int32 vs int64) + gather build: r = t*64+b ----
__global__ void prep_k(const int* __restrict__ in, const int* __restrict__ tg){
    __shared__ int nz[2];
    int tid = threadIdx.x;
    if(tid<2) nz[tid]=0;
    __syncthreads();
    int a=0,b=0;
    for(int i=tid;i<4096;i+=256){ if(in[2*i+1]) a=1; if(tg[2*i+1]) b=1; }
    if(a) atomicOr(&nz[0],1);
    if(b) atomicOr(&nz[1],1);
    __syncthreads();
    bool in64 = (nz[0]==0), tg64 = (nz[1]==0);
    for(int r=tid;r<8192;r+=256){
        int bb=r&63, t=r>>6, p=bb*128+t;
        g_idx_in[r] = in64 ? in[2*p] : in[p];
        g_idx_tg[r] = tg64 ? tg[2*p] : tg[p];
    }
}

// ---- weight reorder: g_WR[m][u>>2][k][u&3][g] = src_m[k][g*512+u] ----
// m: 0-2 encWh l0-2, 3-4 encWx l1-2, 5-7 decWh, 8-9 decWx
__global__ void reorder_k(const float* __restrict__ eWh,const float* __restrict__ eWx,
                          const float* __restrict__ dWh,const float* __restrict__ dWx){
    const int total = 10*512*2048;
    for(int s=blockIdx.x*blockDim.x+threadIdx.x; s<total; s+=gridDim.x*blockDim.x){
        int m = s/(512*2048);
        int rem = s - m*(512*2048);            // k*2048 + g*512 + u
        int u = rem&511, g=(rem>>9)&3, k=rem>>11;
        const float* src; int l;
        if(m<3){src=eWh;l=m;} else if(m<5){src=eWx;l=m-2;}
        else if(m<8){src=dWh;l=m-5;} else {src=dWx;l=m-7;}
        size_t dst = (size_t)m*1048576 + (size_t)(u>>2)*8192 + k*16 + (u&3)*4 + g;
        g_WR[dst] = src[(size_t)l*512*2048 + rem];
    }
}

// ---- generic SGEMM: C = op(gather(A)@B + bias), 128x128x16 tiles ----
// cmode 0: C[r*N+c]; 1: C[(r>>6)*131072 + c*64 + (r&63)]; 2: C[((r&63)*128+(r>>6))*8192+c]
__global__ void __launch_bounds__(256) sgemm_k(
    const float* __restrict__ A,const float* __restrict__ Bm,
    const float* __restrict__ bias,float* __restrict__ C,
    int M,int N,int K,const int* __restrict__ gather,int cmode,int dorelu)
{
    __shared__ float As[16][132];
    __shared__ float Bs[16][128];
    const int tid=threadIdx.x, tx=tid&15, ty=tid>>4;
    const int m0=blockIdx.y<<7, n0=blockIdx.x<<7;
    const float* aptr[2]; int arow[2],akq[2];
    #pragma unroll
    for(int i=0;i<2;i++){
        int L=tid+i*256, row=L>>2, kq=L&3;
        arow[i]=row; akq[i]=kq;
        int gr=m0+row, src = gather ? gather[gr] : gr;
        aptr[i] = A + (size_t)src*K + kq*4;
    }
    const float* bptr[2]; int bkrow[2],bcol[2];
    #pragma unroll
    for(int i=0;i<2;i++){
        int L=tid+i*256, krow=L>>5, col4=(L&31)*4;
        bkrow[i]=krow; bcol[i]=col4;
        bptr[i] = Bm + (size_t)krow*N + n0 + col4;
    }
    unsigned long long acc[8][4];
    #pragma unroll
    for(int i=0;i<8;i++)
        #pragma unroll
        for(int j=0;j<4;j++) acc[i][j]=0ull;

    for(int k0=0;k0<K;k0+=16){
        float4 av[2],bv[2];
        #pragma unroll
        for(int i=0;i<2;i++) av[i]=*(const float4*)(aptr[i]+k0);
        #pragma unroll
        for(int i=0;i<2;i++) bv[i]=*(const float4*)(bptr[i]+(size_t)k0*N);
        __syncthreads();
        #pragma unroll
        for(int i=0;i<2;i++){
            As[akq[i]*4+0][arow[i]]=av[i].x;
            As[akq[i]*4+1][arow[i]]=av[i].y;
            As[akq[i]*4+2][arow[i]]=av[i].z;
            As[akq[i]*4+3][arow[i]]=av[i].w;
            *(float4*)&Bs[bkrow[i]][bcol[i]]=bv[i];
        }
        __syncthreads();
        #pragma unroll
        for(int kk=0;kk<16;kk++){
            float4 a0=*(const float4*)&As[kk][ty*8];
            float4 a1=*(const float4*)&As[kk][ty*8+4];
            ulonglong2 b0=*(const ulonglong2*)&Bs[kk][tx*8];
            ulonglong2 b1=*(const ulonglong2*)&Bs[kk][tx*8+4];
            float aa[8]={a0.x,a0.y,a0.z,a0.w,a1.x,a1.y,a1.z,a1.w};
            #pragma unroll
            for(int i=0;i<8;i++){
                unsigned long long ai=pack2(aa[i],aa[i]);
                fma2(acc[i][0],ai,b0.x); fma2(acc[i][1],ai,b0.y);
                fma2(acc[i][2],ai,b1.x); fma2(acc[i][3],ai,b1.y);
            }
        }
    }
    const int cbase=n0+tx*8;
    float bv8[8];
    #pragma unroll
    for(int j=0;j<8;j++) bv8[j] = bias ? __ldg(&bias[cbase+j]) : 0.f;
    #pragma unroll
    for(int i=0;i<8;i++){
        int r=m0+ty*8+i;
        float v[8];
        #pragma unroll
        for(int j=0;j<4;j++){ float2 f=unpack2(acc[i][j]); v[2*j]=f.x; v[2*j+1]=f.y; }
        #pragma unroll
        for(int j=0;j<8;j++){ v[j]+=bv8[j]; if(dorelu) v[j]=fmaxf(v[j],0.f); }
        if(cmode==0){
            float4* p=(float4*)&C[(size_t)r*N+cbase];
            p[0]=make_float4(v[0],v[1],v[2],v[3]);
            p[1]=make_float4(v[4],v[5],v[6],v[7]);
        } else if(cmode==1){
            size_t base=(size_t)(r>>6)*131072 + (r&63);
            #pragma unroll
            for(int j=0;j<8;j++) C[base+(size_t)(cbase+j)*64]=v[j];
        } else {
            size_t base=(size_t)((r&63)*128+(r>>6))*8192 + cbase;
            float4* p=(float4*)&C[base];
            p[0]=make_float4(v[0],v[1],v[2],v[3]);
            p[1]=make_float4(v[4],v[5],v[6],v[7]);
        }
    }
}

// ---- software grid barrier (128 CTAs, all resident) ----
__device__ __forceinline__ void gbar(){
    __threadfence();
    __syncthreads();
    if(threadIdx.x==0){
        unsigned my = g_gen;
        unsigned old = atomicAdd(&g_count,1u);
        if(old==127u){
            g_count=0;
            __threadfence();
            g_gen = my+1;
        } else {
            while(g_gen==my){ __nanosleep(64); }
        }
    }
    __syncthreads();
}

// ---- persistent recurrence v2: SMEM-resident weights ----
// 128 CTAs x 256 thr. CTA owns units [4c,4c+4); thread = (uu = tid>>6, b = tid&63).
// Dynamic SMEM: sW[5][512][4][4] = 160KB (phase weights) + sHr/sHx 16KB each.
__global__ void __launch_bounds__(256) recurrent_k(
    const float* __restrict__ enc_b,const float* __restrict__ dec_b)
{
    extern __shared__ float smem[];
    float* sW  = smem;           // 40960 floats
    float* sHr = smem + 40960;   // 4096
    float* sHx = smem + 45056;   // 4096

    const int tid=threadIdx.x, b=tid&63, uu=tid>>6;
    const int cta=blockIdx.x;
    const int u = cta*4 + uu;

    // zero parity-0 h
    #pragma unroll
    for(int l=0;l<3;l++) g_h[0][(l*512+u)*64+b]=0.f;
    float cst[3]={0.f,0.f,0.f};
    gbar();

    for(int t=0;t<256;t++){
        const bool enc=(t<128);
        if(t==0 || t==128){
            // load this CTA's phase weight slice (5 matrices x 32KB) into SMEM
            int ph = enc ? 0 : 1;
            __syncthreads();
            #pragma unroll
            for(int j=0;j<5;j++){
                const float4* src=(const float4*)(g_WR + (size_t)(ph*5+j)*1048576
                                                  + (size_t)cta*8192);
                float4* dst=(float4*)(sW + j*8192);
                #pragma unroll
                for(int i=0;i<8;i++) dst[tid + i*256] = __ldg(&src[tid + i*256]);
            }
            __syncthreads();
        }
        const float* ZX = enc ? g_ZXe+(size_t)t*131072 : g_ZXd+(size_t)(t-128)*131072;
        const float* bia= enc ? enc_b : dec_b;
        const int cur=t&1, nxt=cur^1;

        for(int l=0;l<3;l++){
            float a0=__ldg(&bia[l*2048 +        u]);
            float a1=__ldg(&bia[l*2048 +  512 + u]);
            float a2=__ldg(&bia[l*2048 + 1024 + u]);
            float a3=__ldg(&bia[l*2048 + 1536 + u]);
            if(l==0){
                a0 += ZX[(       u)*64+b];
                a1 += ZX[( 512 + u)*64+b];
                a2 += ZX[(1024 + u)*64+b];
                a3 += ZX[(1536 + u)*64+b];
            }
            unsigned long long acc0=pack2(a0,a1), acc1=pack2(a2,a3);

            const float4* hr4=(const float4*)(g_h[cur] + l*32768);
            const float4* hx4=(const float4*)(g_h[nxt] + (l-1)*32768);
            const float* wh = sW + l*8192;
            const float* wx = sW + (2+l)*8192;

            for(int k0=0;k0<512;k0+=64){
                __syncthreads();
                #pragma unroll
                for(int i=0;i<4;i++){
                    int idx=tid+i*256;
                    ((float4*)sHr)[idx]=__ldcg(&hr4[k0*16+idx]);
                }
                if(l){
                    #pragma unroll
                    for(int i=0;i<4;i++){
                        int idx=tid+i*256;
                        ((float4*)sHx)[idx]=__ldcg(&hx4[k0*16+idx]);
                    }
                }
                __syncthreads();
                if(l==0){
                    #pragma unroll 8
                    for(int kk=0;kk<64;kk++){
                        float hk=sHr[kk*64+b];
                        ulonglong2 w=*(const ulonglong2*)&wh[(k0+kk)*16+uu*4];
                        unsigned long long hh=pack2(hk,hk);
                        fma2(acc0,hh,w.x); fma2(acc1,hh,w.y);
                    }
                } else {
                    #pragma unroll 4
                    for(int kk=0;kk<64;kk++){
                        float hk=sHr[kk*64+b];
                        float hx=sHx[kk*64+b];
                        ulonglong2 w=*(const ulonglong2*)&wh[(k0+kk)*16+uu*4];
                        ulonglong2 x=*(const ulonglong2*)&wx[(k0+kk)*16+uu*4];
                        unsigned long long hh=pack2(hk,hk), xx=pack2(hx,hx);
                        fma2(acc0,hh,w.x); fma2(acc1,hh,w.y);
                        fma2(acc0,xx,x.x); fma2(acc1,xx,x.y);
                    }
                }
            }
            float2 g01=unpack2(acc0), g23=unpack2(acc1);
            float ig=sigm(g01.x), fg=sigm(g01.y);
            float gg=tanhf(g23.x), og=sigm(g23.y);
            float cn=fg*cst[l]+ig*gg;
            cst[l]=cn;
            float hn=og*tanhf(cn);
            g_h[nxt][(l*512+u)*64+b]=hn;
            if(l==2 && !enc)
                g_dout[(size_t)((t-128)*64+b)*512+u]=hn;
            gbar();
        }
    }
}

extern "C" void kernel_launch(void* const* d_in, const int* in_sizes, int n_in,
                              void* d_out, int out_size){
    const int*   inputs      =(const int*)  d_in[0];
    const int*   targets     =(const int*)  d_in[1];
    const float* input_embed =(const float*)d_in[2];
    const float* enc_Wd      =(const float*)d_in[3];
    const float* enc_bd      =(const float*)d_in[4];
    const float* enc_Wx      =(const float*)d_in[5];
    const float* enc_Wh      =(const float*)d_in[6];
    const float* enc_b       =(const float*)d_in[7];
    const float* dec_embed   =(const float*)d_in[8];
    const float* dec_Wd      =(const float*)d_in[9];
    const float* dec_bd      =(const float*)d_in[10];
    const float* dec_Wx      =(const float*)d_in[11];
    const float* dec_Wh      =(const float*)d_in[12];
    const float* dec_b       =(const float*)d_in[13];
    const float* out_W1      =(const float*)d_in[14];
    const float* out_b1      =(const float*)d_in[15];
    const float* out_W2      =(const float*)d_in[16];
    const float* out_b2      =(const float*)d_in[17];
    float* out=(float*)d_out;

    float *pX0,*pZXe,*pZXd,*pH1,*pDO;
    int *pIin,*pItg;
    cudaGetSymbolAddress((void**)&pX0, g_X0);
    cudaGetSymbolAddress((void**)&pZXe,g_ZXe);
    cudaGetSymbolAddress((void**)&pZXd,g_ZXd);
    cudaGetSymbolAddress((void**)&pH1, g_H1);
    cudaGetSymbolAddress((void**)&pDO, g_dout);
    cudaGetSymbolAddress((void**)&pIin,g_idx_in);
    cudaGetSymbolAddress((void**)&pItg,g_idx_tg);

    const int RSMEM = 49152 * 4;  // 192KB dynamic smem
    cudaFuncSetAttribute(recurrent_k, cudaFuncAttributeMaxDynamicSharedMemorySize, RSMEM);

    prep_k<<<1,256>>>(inputs,targets);
    reorder_k<<<2048,256>>>(enc_Wh,enc_Wx,dec_Wh,dec_Wx);
    // enc: X0 = relu(gather(embed) @ enc_Wd + enc_bd)
    sgemm_k<<<dim3(4,64),256>>>(input_embed,enc_Wd,enc_bd,pX0,8192,512,64,pIin,0,1);
    // enc: ZXe = X0 @ enc_Wx[0]   (layout [t][col][b])
    sgemm_k<<<dim3(16,64),256>>>(pX0,enc_Wx,nullptr,pZXe,8192,2048,512,nullptr,1,0);
    // dec: X0 = relu(gather(dec_embed) @ dec_Wd + dec_bd)
    sgemm_k<<<dim3(4,64),256>>>(dec_embed,dec_Wd,dec_bd,pX0,8192,512,2048,pItg,0,1);
    // dec: ZXd = X0 @ dec_Wx[0]
    sgemm_k<<<dim3(16,64),256>>>(pX0,dec_Wx,nullptr,pZXd,8192,2048,512,nullptr,1,0);
    // recurrence (enc 128 + dec 128 steps), SMEM-resident weights
    recurrent_k<<<128,256,RSMEM>>>(enc_b,dec_b);
    // head: H1 = relu(dout @ out_W1 + out_b1)
    sgemm_k<<<dim3(16,64),256>>>(pDO,out_W1,out_b1,pH1,8192,2048,512,nullptr,0,1);
    // head: out = relu(H1 @ out_W2 + out_b2), remapped to [B][T][P]
    sgemm_k<<<dim3(64,64),256>>>(pH1,out_W2,out_b2,out,8192,8192,2048,nullptr,2,1);
}

// round 13
// speedup vs baseline: 4.3659x; 1.0789x over previous
#include <cuda_runtime.h>
#include <cuda_bf16.h>
#include <cstdint>

#define MATSZ (512*512*4)

__device__ __align__(16) float g_X0 [8192*512];
__device__ __align__(16) float g_ZXe[128*2048*64];
__device__ __align__(16) float g_ZXd[128*2048*64];
__device__ __align__(16) float g_H1 [(size_t)8192*2048];
__device__ __align__(16) float g_dout[8192*512];
__device__ __align__(16) float g_WR [(size_t)10*MATSZ];   // [m][cta128][k512][uu4][g4]
__device__ __align__(16) float g_h[2][3*512*64];
__device__ int g_idx_in[8192];
__device__ int g_idx_tg[8192];
__device__ unsigned g_count = 0;
__device__ volatile unsigned g_gen = 0;
__device__ __align__(128) unsigned g_flag[128*32];        // per-CTA epoch, 128B apart

__device__ __forceinline__ unsigned long long pack2(float lo, float hi){
    unsigned long long r;
    asm("mov.b64 %0,{%1,%2};":"=l"(r):"r"(__float_as_uint(lo)),"r"(__float_as_uint(hi)));
    return r;
}
__device__ __forceinline__ void fma2(unsigned long long&d,unsigned long long a,unsigned long long b){
    asm("fma.rn.f32x2 %0,%1,%2,%0;":"+l"(d):"l"(a),"l"(b));
}
__device__ __forceinline__ float2 unpack2(unsigned long long v){
    unsigned lo,hi; asm("mov.b64 {%0,%1},%2;":"=r"(lo),"=r"(hi):"l"(v));
    return make_float2(__uint_as_float(lo),__uint_as_float(hi));
}
__device__ __forceinline__ float sigm(float x){ return __fdividef(1.f,1.f+__expf(-x)); }

// ---- prep: dtype sniff (int32 vs int64) + gather build: r = t*64+b ----
__global__ void prep_k(const int* __restrict__ in, const int* __restrict__ tg){
    __shared__ int nz[2];
    int tid = threadIdx.x;
    if(tid<2) nz[tid]=0;
    __syncthreads();
    int a=0,b=0;
    for(int i=tid;i<4096;i+=256){ if(in[2*i+1]) a=1; if(tg[2*i+1]) b=1; }
    if(a) atomicOr(&nz[0],1);
    if(b) atomicOr(&nz[1],1);
    __syncthreads();
    bool in64 = (nz[0]==0), tg64 = (nz[1]==0);
    for(int r=tid;r<8192;r+=256){
        int bb=r&63, t=r>>6, p=bb*128+t;
        g_idx_in[r] = in64 ? in[2*p] : in[p];
        g_idx_tg[r] = tg64 ? tg[2*p] : tg[p];
    }
}

// ---- weight reorder: g_WR[m][u>>2][k][u&3][g] = src_m[k][g*512+u] ----
__global__ void reorder_k(const float* __restrict__ eWh,const float* __restrict__ eWx,
                          const float* __restrict__ dWh,const float* __restrict__ dWx){
    const int total = 10*512*2048;
    for(int s=blockIdx.x*blockDim.x+threadIdx.x; s<total; s+=gridDim.x*blockDim.x){
        int m = s/(512*2048);
        int rem = s - m*(512*2048);            // k*2048 + g*512 + u
        int u = rem&511, g=(rem>>9)&3, k=rem>>11;
        const float* src; int l;
        if(m<3){src=eWh;l=m;} else if(m<5){src=eWx;l=m-2;}
        else if(m<8){src=dWh;l=m-5;} else {src=dWx;l=m-7;}
        size_t dst = (size_t)m*1048576 + (size_t)(u>>2)*8192 + k*16 + (u&3)*4 + g;
        g_WR[dst] = src[(size_t)l*512*2048 + rem];
    }
}

// ---- generic SGEMM: C = op(gather(A)@B + bias), 128x128x16 tiles ----
__global__ void __launch_bounds__(256) sgemm_k(
    const float* __restrict__ A,const float* __restrict__ Bm,
    const float* __restrict__ bias,float* __restrict__ C,
    int M,int N,int K,const int* __restrict__ gather,int cmode,int dorelu)
{
    __shared__ float As[16][132];
    __shared__ float Bs[16][128];
    const int tid=threadIdx.x, tx=tid&15, ty=tid>>4;
    const int m0=blockIdx.y<<7, n0=blockIdx.x<<7;
    const float* aptr[2]; int arow[2],akq[2];
    #pragma unroll
    for(int i=0;i<2;i++){
        int L=tid+i*256, row=L>>2, kq=L&3;
        arow[i]=row; akq[i]=kq;
        int gr=m0+row, src = gather ? gather[gr] : gr;
        aptr[i] = A + (size_t)src*K + kq*4;
    }
    const float* bptr[2]; int bkrow[2],bcol[2];
    #pragma unroll
    for(int i=0;i<2;i++){
        int L=tid+i*256, krow=L>>5, col4=(L&31)*4;
        bkrow[i]=krow; bcol[i]=col4;
        bptr[i] = Bm + (size_t)krow*N + n0 + col4;
    }
    unsigned long long acc[8][4];
    #pragma unroll
    for(int i=0;i<8;i++)
        #pragma unroll
        for(int j=0;j<4;j++) acc[i][j]=0ull;

    for(int k0=0;k0<K;k0+=16){
        float4 av[2],bv[2];
        #pragma unroll
        for(int i=0;i<2;i++) av[i]=*(const float4*)(aptr[i]+k0);
        #pragma unroll
        for(int i=0;i<2;i++) bv[i]=*(const float4*)(bptr[i]+(size_t)k0*N);
        __syncthreads();
        #pragma unroll
        for(int i=0;i<2;i++){
            As[akq[i]*4+0][arow[i]]=av[i].x;
            As[akq[i]*4+1][arow[i]]=av[i].y;
            As[akq[i]*4+2][arow[i]]=av[i].z;
            As[akq[i]*4+3][arow[i]]=av[i].w;
            *(float4*)&Bs[bkrow[i]][bcol[i]]=bv[i];
        }
        __syncthreads();
        #pragma unroll
        for(int kk=0;kk<16;kk++){
            float4 a0=*(const float4*)&As[kk][ty*8];
            float4 a1=*(const float4*)&As[kk][ty*8+4];
            ulonglong2 b0=*(const ulonglong2*)&Bs[kk][tx*8];
            ulonglong2 b1=*(const ulonglong2*)&Bs[kk][tx*8+4];
            float aa[8]={a0.x,a0.y,a0.z,a0.w,a1.x,a1.y,a1.z,a1.w};
            #pragma unroll
            for(int i=0;i<8;i++){
                unsigned long long ai=pack2(aa[i],aa[i]);
                fma2(acc[i][0],ai,b0.x); fma2(acc[i][1],ai,b0.y);
                fma2(acc[i][2],ai,b1.x); fma2(acc[i][3],ai,b1.y);
            }
        }
    }
    const int cbase=n0+tx*8;
    float bv8[8];
    #pragma unroll
    for(int j=0;j<8;j++) bv8[j] = bias ? __ldg(&bias[cbase+j]) : 0.f;
    #pragma unroll
    for(int i=0;i<8;i++){
        int r=m0+ty*8+i;
        float v[8];
        #pragma unroll
        for(int j=0;j<4;j++){ float2 f=unpack2(acc[i][j]); v[2*j]=f.x; v[2*j+1]=f.y; }
        #pragma unroll
        for(int j=0;j<8;j++){ v[j]+=bv8[j]; if(dorelu) v[j]=fmaxf(v[j],0.f); }
        if(cmode==0){
            float4* p=(float4*)&C[(size_t)r*N+cbase];
            p[0]=make_float4(v[0],v[1],v[2],v[3]);
            p[1]=make_float4(v[4],v[5],v[6],v[7]);
        } else if(cmode==1){
            size_t base=(size_t)(r>>6)*131072 + (r&63);
            #pragma unroll
            for(int j=0;j<8;j++) C[base+(size_t)(cbase+j)*64]=v[j];
        } else {
            size_t base=(size_t)((r&63)*128+(r>>6))*8192 + cbase;
            float4* p=(float4*)&C[base];
            p[0]=make_float4(v[0],v[1],v[2],v[3]);
            p[1]=make_float4(v[4],v[5],v[6],v[7]);
        }
    }
}

// ---- legacy central barrier (used once at init) ----
__device__ __forceinline__ void gbar_legacy(){
    __threadfence();
    __syncthreads();
    if(threadIdx.x==0){
        unsigned my = g_gen;
        unsigned old = atomicAdd(&g_count,1u);
        if(old==127u){
            g_count=0;
            __threadfence();
            g_gen = my+1;
        } else {
            while(g_gen==my){ __nanosleep(64); }
        }
    }
    __syncthreads();
}

// ---- distributed flag barrier: release/acquire, one flag per CTA ----
__device__ __forceinline__ void gbar2(int cta, unsigned ep){
    __syncthreads();
    if(threadIdx.x==0){
        asm volatile("st.release.gpu.u32 [%0], %1;"
                     :: "l"(g_flag + cta*32), "r"(ep) : "memory");
    }
    if(threadIdx.x<128){
        unsigned v;
        do {
            asm volatile("ld.acquire.gpu.u32 %0, [%1];"
                         : "=r"(v) : "l"(g_flag + threadIdx.x*32) : "memory");
        } while((int)(v-ep)<0);
    }
    __syncthreads();
}

// ---- persistent recurrence v3: SMEM weights + flag barrier + double-buffered h ----
// 128 CTAs x 256 thr. CTA owns units [4c,4c+4); thread = (uu = tid>>6, b = tid&63).
// smem: sW 160KB | hrbuf[2] 32KB | hxbuf[2] 32KB  = 224KB
__global__ void __launch_bounds__(256) recurrent_k(
    const float* __restrict__ enc_b,const float* __restrict__ dec_b)
{
    extern __shared__ float smem[];
    float* sW = smem;                                   // 40960 floats
    float* bufR[2] = { smem+40960, smem+45056 };        // 4096 each
    float* bufX[2] = { smem+49152, smem+53248 };

    const int tid=threadIdx.x, b=tid&63, uu=tid>>6;
    const int cta=blockIdx.x;
    const int u = cta*4 + uu;

    // reset parity-0 h and this CTA's flag (replay-safe), then full barrier
    #pragma unroll
    for(int l=0;l<3;l++) g_h[0][(l*512+u)*64+b]=0.f;
    if(tid==0) g_flag[cta*32]=0u;
    float cst[3]={0.f,0.f,0.f};
    gbar_legacy();
    unsigned ep=0;

    for(int t=0;t<256;t++){
        const bool enc=(t<128);
        if(t==0 || t==128){
            int ph = enc ? 0 : 1;
            #pragma unroll
            for(int j=0;j<5;j++){
                const float4* src=(const float4*)(g_WR + (size_t)(ph*5+j)*1048576
                                                  + (size_t)cta*8192);
                float4* dst=(float4*)(sW + j*8192);
                #pragma unroll
                for(int i=0;i<8;i++) dst[tid + i*256] = __ldg(&src[tid + i*256]);
            }
            __syncthreads();
        }
        const float* ZX = enc ? g_ZXe+(size_t)t*131072 : g_ZXd+(size_t)(t-128)*131072;
        const float* bia= enc ? enc_b : dec_b;
        const int cur=t&1, nxt=cur^1;

        for(int l=0;l<3;l++){
            float a0=__ldg(&bia[l*2048 +        u]);
            float a1=__ldg(&bia[l*2048 +  512 + u]);
            float a2=__ldg(&bia[l*2048 + 1024 + u]);
            float a3=__ldg(&bia[l*2048 + 1536 + u]);
            if(l==0){
                a0 += __ldg(&ZX[(       u)*64+b]);
                a1 += __ldg(&ZX[( 512 + u)*64+b]);
                a2 += __ldg(&ZX[(1024 + u)*64+b]);
                a3 += __ldg(&ZX[(1536 + u)*64+b]);
            }
            unsigned long long acc0=pack2(a0,a1), acc1=pack2(a2,a3);

            const float4* hr4=(const float4*)(g_h[cur] + l*32768);
            const float4* hx4=(const float4*)(g_h[nxt] + (l-1)*32768);
            const float* wh = sW + l*8192;
            const float* wx = sW + (2+l)*8192;

            // prologue: chunk 0 -> buf 0
            float4 rh[4], rx[4];
            #pragma unroll
            for(int i=0;i<4;i++) rh[i]=__ldcg(&hr4[tid+i*256]);
            if(l){
                #pragma unroll
                for(int i=0;i<4;i++) rx[i]=__ldcg(&hx4[tid+i*256]);
            }
            #pragma unroll
            for(int i=0;i<4;i++) ((float4*)bufR[0])[tid+i*256]=rh[i];
            if(l){
                #pragma unroll
                for(int i=0;i<4;i++) ((float4*)bufX[0])[tid+i*256]=rx[i];
            }

            for(int c=0;c<8;c++){
                // prefetch chunk c+1 into registers (overlaps compute)
                if(c<7){
                    #pragma unroll
                    for(int i=0;i<4;i++) rh[i]=__ldcg(&hr4[(c+1)*1024+tid+i*256]);
                    if(l){
                        #pragma unroll
                        for(int i=0;i<4;i++) rx[i]=__ldcg(&hx4[(c+1)*1024+tid+i*256]);
                    }
                }
                __syncthreads();   // buf[c&1] visible to all
                const float* sr=bufR[c&1];
                const float* sx=bufX[c&1];
                const int k0=c*64;
                if(l==0){
                    #pragma unroll 8
                    for(int kk=0;kk<64;kk++){
                        float hk=sr[kk*64+b];
                        ulonglong2 w=*(const ulonglong2*)&wh[(k0+kk)*16+uu*4];
                        unsigned long long hh=pack2(hk,hk);
                        fma2(acc0,hh,w.x); fma2(acc1,hh,w.y);
                    }
                } else {
                    #pragma unroll 4
                    for(int kk=0;kk<64;kk++){
                        float hk=sr[kk*64+b];
                        float hx=sx[kk*64+b];
                        ulonglong2 w=*(const ulonglong2*)&wh[(k0+kk)*16+uu*4];
                        ulonglong2 x=*(const ulonglong2*)&wx[(k0+kk)*16+uu*4];
                        unsigned long long hh=pack2(hk,hk), xx=pack2(hx,hx);
                        fma2(acc0,hh,w.x); fma2(acc1,hh,w.y);
                        fma2(acc0,xx,x.x); fma2(acc1,xx,x.y);
                    }
                }
                // store prefetched chunk into the other buffer
                // (safe: its last readers passed the syncthreads above)
                if(c<7){
                    #pragma unroll
                    for(int i=0;i<4;i++) ((float4*)bufR[(c+1)&1])[tid+i*256]=rh[i];
                    if(l){
                        #pragma unroll
                        for(int i=0;i<4;i++) ((float4*)bufX[(c+1)&1])[tid+i*256]=rx[i];
                    }
                }
            }
            float2 g01=unpack2(acc0), g23=unpack2(acc1);
            float ig=sigm(g01.x), fg=sigm(g01.y);
            float gg=tanhf(g23.x), og=sigm(g23.y);
            float cn=fg*cst[l]+ig*gg;
            cst[l]=cn;
            float hn=og*tanhf(cn);
            g_h[nxt][(l*512+u)*64+b]=hn;
            if(l==2 && !enc)
                g_dout[(size_t)((t-128)*64+b)*512+u]=hn;
            gbar2(cta, ++ep);
        }
    }
}

extern "C" void kernel_launch(void* const* d_in, const int* in_sizes, int n_in,
                              void* d_out, int out_size){
    const int*   inputs      =(const int*)  d_in[0];
    const int*   targets     =(const int*)  d_in[1];
    const float* input_embed =(const float*)d_in[2];
    const float* enc_Wd      =(const float*)d_in[3];
    const float* enc_bd      =(const float*)d_in[4];
    const float* enc_Wx      =(const float*)d_in[5];
    const float* enc_Wh      =(const float*)d_in[6];
    const float* enc_b       =(const float*)d_in[7];
    const float* dec_embed   =(const float*)d_in[8];
    const float* dec_Wd      =(const float*)d_in[9];
    const float* dec_bd      =(const float*)d_in[10];
    const float* dec_Wx      =(const float*)d_in[11];
    const float* dec_Wh      =(const float*)d_in[12];
    const float* dec_b       =(const float*)d_in[13];
    const float* out_W1      =(const float*)d_in[14];
    const float* out_b1      =(const float*)d_in[15];
    const float* out_W2      =(const float*)d_in[16];
    const float* out_b2      =(const float*)d_in[17];
    float* out=(float*)d_out;

    float *pX0,*pZXe,*pZXd,*pH1,*pDO;
    int *pIin,*pItg;
    cudaGetSymbolAddress((void**)&pX0, g_X0);
    cudaGetSymbolAddress((void**)&pZXe,g_ZXe);
    cudaGetSymbolAddress((void**)&pZXd,g_ZXd);
    cudaGetSymbolAddress((void**)&pH1, g_H1);
    cudaGetSymbolAddress((void**)&pDO, g_dout);
    cudaGetSymbolAddress((void**)&pIin,g_idx_in);
    cudaGetSymbolAddress((void**)&pItg,g_idx_tg);

    const int RSMEM = 57344 * 4;  // 224KB dynamic smem
    cudaFuncSetAttribute(recurrent_k, cudaFuncAttributeMaxDynamicSharedMemorySize, RSMEM);

    prep_k<<<1,256>>>(inputs,targets);
    reorder_k<<<2048,256>>>(enc_Wh,enc_Wx,dec_Wh,dec_Wx);
    // enc: X0 = relu(gather(embed) @ enc_Wd + enc_bd)
    sgemm_k<<<dim3(4,64),256>>>(input_embed,enc_Wd,enc_bd,pX0,8192,512,64,pIin,0,1);
    // enc: ZXe = X0 @ enc_Wx[0]   (layout [t][col][b])
    sgemm_k<<<dim3(16,64),256>>>(pX0,enc_Wx,nullptr,pZXe,8192,2048,512,nullptr,1,0);
    // dec: X0 = relu(gather(dec_embed) @ dec_Wd + dec_bd)
    sgemm_k<<<dim3(4,64),256>>>(dec_embed,dec_Wd,dec_bd,pX0,8192,512,2048,pItg,0,1);
    // dec: ZXd = X0 @ dec_Wx[0]
    sgemm_k<<<dim3(16,64),256>>>(pX0,dec_Wx,nullptr,pZXd,8192,2048,512,nullptr,1,0);
    // recurrence (enc 128 + dec 128 steps)
    recurrent_k<<<128,256,RSMEM>>>(enc_b,dec_b);
    // head: H1 = relu(dout @ out_W1 + out_b1)
    sgemm_k<<<dim3(16,64),256>>>(pDO,out_W1,out_b1,pH1,8192,2048,512,nullptr,0,1);
    // head: out = relu(H1 @ out_W2 + out_b2), remapped to [B][T][P]
    sgemm_k<<<dim3(64,64),256>>>(pH1,out_W2,out_b2,out,8192,8192,2048,nullptr,2,1);
}

// round 14
// speedup vs baseline: 4.9020x; 1.1228x over previous
#include <cuda_runtime.h>
#include <cuda_bf16.h>
#include <cstdint>

#define MATSZ (512*512*4)

__device__ __align__(16) float g_X0 [8192*512];
__device__ __align__(16) float g_ZXe[128*2048*64];
__device__ __align__(16) float g_ZXd[128*2048*64];
__device__ __align__(16) float g_H1 [(size_t)8192*2048];
__device__ __align__(16) float g_dout[8192*512];
__device__ __align__(16) float g_WR [(size_t)10*MATSZ];   // [m][cta128][k512][uu4][g4]
__device__ __align__(16) float g_h[2][3*512*64];
__device__ int g_idx_in[8192];
__device__ int g_idx_tg[8192];
__device__ unsigned g_count = 0;
__device__ volatile unsigned g_gen = 0;
__device__ __align__(128) unsigned g_flag[128*32];        // per-CTA epoch, 128B apart

__device__ __forceinline__ unsigned long long pack2(float lo, float hi){
    unsigned long long r;
    asm("mov.b64 %0,{%1,%2};":"=l"(r):"r"(__float_as_uint(lo)),"r"(__float_as_uint(hi)));
    return r;
}
__device__ __forceinline__ void fma2(unsigned long long&d,unsigned long long a,unsigned long long b){
    asm("fma.rn.f32x2 %0,%1,%2,%0;":"+l"(d):"l"(a),"l"(b));
}
__device__ __forceinline__ float2 unpack2(unsigned long long v){
    unsigned lo,hi; asm("mov.b64 {%0,%1},%2;":"=r"(lo),"=r"(hi):"l"(v));
    return make_float2(__uint_as_float(lo),__uint_as_float(hi));
}
__device__ __forceinline__ float sigm(float x){ return __fdividef(1.f,1.f+__expf(-x)); }

// ---- fused prep (block 0) + weight reorder (all blocks) ----
// prep: dtype sniff int32/int64, gather r = t*64+b.
// reorder: g_WR[m][u>>2][k][u&3][g] = src_m[k][g*512+u]
__global__ void prep_reorder_k(const int* __restrict__ in, const int* __restrict__ tg,
                               const float* __restrict__ eWh,const float* __restrict__ eWx,
                               const float* __restrict__ dWh,const float* __restrict__ dWx){
    int tid = threadIdx.x;
    if(blockIdx.x==0){
        __shared__ int nz[2];
        if(tid<2) nz[tid]=0;
        __syncthreads();
        int a=0,b=0;
        for(int i=tid;i<4096;i+=256){ if(in[2*i+1]) a=1; if(tg[2*i+1]) b=1; }
        if(a) atomicOr(&nz[0],1);
        if(b) atomicOr(&nz[1],1);
        __syncthreads();
        bool in64=(nz[0]==0), tg64=(nz[1]==0);
        for(int r=tid;r<8192;r+=256){
            int bb=r&63, t=r>>6, p=bb*128+t;
            g_idx_in[r] = in64 ? in[2*p] : in[p];
            g_idx_tg[r] = tg64 ? tg[2*p] : tg[p];
        }
    }
    const int total = 10*512*2048;
    for(int s=blockIdx.x*blockDim.x+tid; s<total; s+=gridDim.x*blockDim.x){
        int m = s/(512*2048);
        int rem = s - m*(512*2048);            // k*2048 + g*512 + u
        int u = rem&511, g=(rem>>9)&3, k=rem>>11;
        const float* src; int l;
        if(m<3){src=eWh;l=m;} else if(m<5){src=eWx;l=m-2;}
        else if(m<8){src=dWh;l=m-5;} else {src=dWx;l=m-7;}
        size_t dst = (size_t)m*1048576 + (size_t)(u>>2)*8192 + k*16 + (u&3)*4 + g;
        g_WR[dst] = src[(size_t)l*512*2048 + rem];
    }
}

// ---- generic SGEMM: C = op(gather(A)@B + bias), 128x128x16 tiles ----
__global__ void __launch_bounds__(256) sgemm_k(
    const float* __restrict__ A,const float* __restrict__ Bm,
    const float* __restrict__ bias,float* __restrict__ C,
    int M,int N,int K,const int* __restrict__ gather,int cmode,int dorelu)
{
    __shared__ float As[16][132];
    __shared__ float Bs[16][128];
    const int tid=threadIdx.x, tx=tid&15, ty=tid>>4;
    const int m0=blockIdx.y<<7, n0=blockIdx.x<<7;
    const float* aptr[2]; int arow[2],akq[2];
    #pragma unroll
    for(int i=0;i<2;i++){
        int L=tid+i*256, row=L>>2, kq=L&3;
        arow[i]=row; akq[i]=kq;
        int gr=m0+row, src = gather ? gather[gr] : gr;
        aptr[i] = A + (size_t)src*K + kq*4;
    }
    const float* bptr[2]; int bkrow[2],bcol[2];
    #pragma unroll
    for(int i=0;i<2;i++){
        int L=tid+i*256, krow=L>>5, col4=(L&31)*4;
        bkrow[i]=krow; bcol[i]=col4;
        bptr[i] = Bm + (size_t)krow*N + n0 + col4;
    }
    unsigned long long acc[8][4];
    #pragma unroll
    for(int i=0;i<8;i++)
        #pragma unroll
        for(int j=0;j<4;j++) acc[i][j]=0ull;

    for(int k0=0;k0<K;k0+=16){
        float4 av[2],bv[2];
        #pragma unroll
        for(int i=0;i<2;i++) av[i]=*(const float4*)(aptr[i]+k0);
        #pragma unroll
        for(int i=0;i<2;i++) bv[i]=*(const float4*)(bptr[i]+(size_t)k0*N);
        __syncthreads();
        #pragma unroll
        for(int i=0;i<2;i++){
            As[akq[i]*4+0][arow[i]]=av[i].x;
            As[akq[i]*4+1][arow[i]]=av[i].y;
            As[akq[i]*4+2][arow[i]]=av[i].z;
            As[akq[i]*4+3][arow[i]]=av[i].w;
            *(float4*)&Bs[bkrow[i]][bcol[i]]=bv[i];
        }
        __syncthreads();
        #pragma unroll
        for(int kk=0;kk<16;kk++){
            float4 a0=*(const float4*)&As[kk][ty*8];
            float4 a1=*(const float4*)&As[kk][ty*8+4];
            ulonglong2 b0=*(const ulonglong2*)&Bs[kk][tx*8];
            ulonglong2 b1=*(const ulonglong2*)&Bs[kk][tx*8+4];
            float aa[8]={a0.x,a0.y,a0.z,a0.w,a1.x,a1.y,a1.z,a1.w};
            #pragma unroll
            for(int i=0;i<8;i++){
                unsigned long long ai=pack2(aa[i],aa[i]);
                fma2(acc[i][0],ai,b0.x); fma2(acc[i][1],ai,b0.y);
                fma2(acc[i][2],ai,b1.x); fma2(acc[i][3],ai,b1.y);
            }
        }
    }
    const int cbase=n0+tx*8;
    float bv8[8];
    #pragma unroll
    for(int j=0;j<8;j++) bv8[j] = bias ? __ldg(&bias[cbase+j]) : 0.f;
    #pragma unroll
    for(int i=0;i<8;i++){
        int r=m0+ty*8+i;
        float v[8];
        #pragma unroll
        for(int j=0;j<4;j++){ float2 f=unpack2(acc[i][j]); v[2*j]=f.x; v[2*j+1]=f.y; }
        #pragma unroll
        for(int j=0;j<8;j++){ v[j]+=bv8[j]; if(dorelu) v[j]=fmaxf(v[j],0.f); }
        if(cmode==0){
            float4* p=(float4*)&C[(size_t)r*N+cbase];
            p[0]=make_float4(v[0],v[1],v[2],v[3]);
            p[1]=make_float4(v[4],v[5],v[6],v[7]);
        } else if(cmode==1){
            size_t base=(size_t)(r>>6)*131072 + (r&63);
            #pragma unroll
            for(int j=0;j<8;j++) C[base+(size_t)(cbase+j)*64]=v[j];
        } else {
            size_t base=(size_t)((r&63)*128+(r>>6))*8192 + cbase;
            float4* p=(float4*)&C[base];
            p[0]=make_float4(v[0],v[1],v[2],v[3]);
            p[1]=make_float4(v[4],v[5],v[6],v[7]);
        }
    }
}

// ---- legacy central barrier (init only) ----
__device__ __forceinline__ void gbar_legacy(){
    __threadfence();
    __syncthreads();
    if(threadIdx.x==0){
        unsigned my = g_gen;
        unsigned old = atomicAdd(&g_count,1u);
        if(old==127u){
            g_count=0;
            __threadfence();
            g_gen = my+1;
        } else {
            while(g_gen==my){ __nanosleep(64); }
        }
    }
    __syncthreads();
}

// ---- distributed flag barrier: release/acquire, one flag per CTA ----
__device__ __forceinline__ void gbar2(int cta, unsigned ep){
    __syncthreads();
    if(threadIdx.x==0){
        asm volatile("st.release.gpu.u32 [%0], %1;"
                     :: "l"(g_flag + cta*32), "r"(ep) : "memory");
    }
    {
        unsigned v;
        do {
            asm volatile("ld.acquire.gpu.u32 %0, [%1];"
                         : "=r"(v) : "l"(g_flag + threadIdx.x*32) : "memory");
        } while((int)(v-ep)<0);
    }
    __syncthreads();
}

// ---- persistent recurrence v4: 128 thr/CTA, 2 units/thread ----
// 128 CTAs. CTA owns units [4c,4c+4); thread = (half = tid>>6, b = tid&63),
// units u0 = 4c + half*2 and u0+1.
// smem: sW 160KB | sHr 16KB | sHx 16KB = 192KB
__global__ void __launch_bounds__(128) recurrent_k(
    const float* __restrict__ enc_b,const float* __restrict__ dec_b)
{
    extern __shared__ float smem[];
    float* sW  = smem;           // 40960 floats
    float* sHr = smem + 40960;   // 4096
    float* sHx = smem + 45056;   // 4096

    const int tid=threadIdx.x, b=tid&63, half=tid>>6;
    const int cta=blockIdx.x;
    const int u0 = cta*4 + half*2;

    #pragma unroll
    for(int l=0;l<3;l++){
        g_h[0][(l*512+u0  )*64+b]=0.f;
        g_h[0][(l*512+u0+1)*64+b]=0.f;
    }
    if(tid==0) g_flag[cta*32]=0u;
    float cst[3][2]={{0,0},{0,0},{0,0}};
    gbar_legacy();
    unsigned ep=0;

    for(int t=0;t<256;t++){
        const bool enc=(t<128);
        if(t==0 || t==128){
            int ph = enc ? 0 : 1;
            #pragma unroll
            for(int j=0;j<5;j++){
                const float4* src=(const float4*)(g_WR + (size_t)(ph*5+j)*1048576
                                                  + (size_t)cta*8192);
                float4* dst=(float4*)(sW + j*8192);
                #pragma unroll
                for(int i=0;i<16;i++) dst[tid + i*128] = __ldg(&src[tid + i*128]);
            }
            __syncthreads();
        }
        const float* ZX = enc ? g_ZXe+(size_t)t*131072 : g_ZXd+(size_t)(t-128)*131072;
        const float* bia= enc ? enc_b : dec_b;
        const int cur=t&1, nxt=cur^1;

        for(int l=0;l<3;l++){
            float a4[2][4];
            #pragma unroll
            for(int cc=0;cc<2;cc++)
                #pragma unroll
                for(int g=0;g<4;g++){
                    float x=__ldg(&bia[l*2048 + g*512 + u0+cc]);
                    if(l==0) x += __ldg(&ZX[(g*512 + u0+cc)*64+b]);
                    a4[cc][g]=x;
                }
            unsigned long long ac[2][2];
            #pragma unroll
            for(int cc=0;cc<2;cc++){
                ac[cc][0]=pack2(a4[cc][0],a4[cc][1]);
                ac[cc][1]=pack2(a4[cc][2],a4[cc][3]);
            }
            const float4* hr4=(const float4*)(g_h[cur] + l*32768);
            const float4* hx4=(const float4*)(g_h[nxt] + (l-1)*32768);
            const float* wh = sW + l*8192;
            const float* wx = sW + (2+l)*8192;

            // prologue: chunk 0 -> smem
            float4 rh[8], rx[8];
            #pragma unroll
            for(int i=0;i<8;i++) rh[i]=__ldcg(&hr4[tid+i*128]);
            if(l){
                #pragma unroll
                for(int i=0;i<8;i++) rx[i]=__ldcg(&hx4[tid+i*128]);
            }
            #pragma unroll
            for(int i=0;i<8;i++) ((float4*)sHr)[tid+i*128]=rh[i];
            if(l){
                #pragma unroll
                for(int i=0;i<8;i++) ((float4*)sHx)[tid+i*128]=rx[i];
            }

            for(int c=0;c<8;c++){
                if(c<7){
                    #pragma unroll
                    for(int i=0;i<8;i++) rh[i]=__ldcg(&hr4[(c+1)*1024+tid+i*128]);
                    if(l){
                        #pragma unroll
                        for(int i=0;i<8;i++) rx[i]=__ldcg(&hx4[(c+1)*1024+tid+i*128]);
                    }
                }
                __syncthreads();   // chunk c stores visible
                const int k0=c*64;
                if(l==0){
                    #pragma unroll 8
                    for(int kk=0;kk<64;kk++){
                        float hk=sHr[kk*64+b];
                        unsigned long long hh=pack2(hk,hk);
                        const float* wp=&wh[(k0+kk)*16+half*8];
                        ulonglong2 w0=*(const ulonglong2*)wp;
                        ulonglong2 w1=*(const ulonglong2*)(wp+4);
                        fma2(ac[0][0],hh,w0.x); fma2(ac[0][1],hh,w0.y);
                        fma2(ac[1][0],hh,w1.x); fma2(ac[1][1],hh,w1.y);
                    }
                } else {
                    #pragma unroll 4
                    for(int kk=0;kk<64;kk++){
                        float hk=sHr[kk*64+b];
                        float hxv=sHx[kk*64+b];
                        unsigned long long hh=pack2(hk,hk), xx=pack2(hxv,hxv);
                        const float* wp=&wh[(k0+kk)*16+half*8];
                        const float* xp=&wx[(k0+kk)*16+half*8];
                        ulonglong2 w0=*(const ulonglong2*)wp;
                        ulonglong2 w1=*(const ulonglong2*)(wp+4);
                        ulonglong2 x0=*(const ulonglong2*)xp;
                        ulonglong2 x1=*(const ulonglong2*)(xp+4);
                        fma2(ac[0][0],hh,w0.x); fma2(ac[0][1],hh,w0.y);
                        fma2(ac[1][0],hh,w1.x); fma2(ac[1][1],hh,w1.y);
                        fma2(ac[0][0],xx,x0.x); fma2(ac[0][1],xx,x0.y);
                        fma2(ac[1][0],xx,x1.x); fma2(ac[1][1],xx,x1.y);
                    }
                }
                if(c<7){
                    __syncthreads();   // all done reading chunk c
                    #pragma unroll
                    for(int i=0;i<8;i++) ((float4*)sHr)[tid+i*128]=rh[i];
                    if(l){
                        #pragma unroll
                        for(int i=0;i<8;i++) ((float4*)sHx)[tid+i*128]=rx[i];
                    }
                }
            }
            #pragma unroll
            for(int cc=0;cc<2;cc++){
                float2 g01=unpack2(ac[cc][0]);
                float2 g23=unpack2(ac[cc][1]);
                float ig=sigm(g01.x), fg=sigm(g01.y);
                float gg=tanhf(g23.x), og=sigm(g23.y);
                float cn=fg*cst[l][cc]+ig*gg;
                cst[l][cc]=cn;
                float hn=og*tanhf(cn);
                g_h[nxt][(l*512+u0+cc)*64+b]=hn;
                if(l==2 && !enc)
                    g_dout[(size_t)((t-128)*64+b)*512+u0+cc]=hn;
            }
            gbar2(cta, ++ep);
        }
    }
}

extern "C" void kernel_launch(void* const* d_in, const int* in_sizes, int n_in,
                              void* d_out, int out_size){
    const int*   inputs      =(const int*)  d_in[0];
    const int*   targets     =(const int*)  d_in[1];
    const float* input_embed =(const float*)d_in[2];
    const float* enc_Wd      =(const float*)d_in[3];
    const float* enc_bd      =(const float*)d_in[4];
    const float* enc_Wx      =(const float*)d_in[5];
    const float* enc_Wh      =(const float*)d_in[6];
    const float* enc_b       =(const float*)d_in[7];
    const float* dec_embed   =(const float*)d_in[8];
    const float* dec_Wd      =(const float*)d_in[9];
    const float* dec_bd      =(const float*)d_in[10];
    const float* dec_Wx      =(const float*)d_in[11];
    const float* dec_Wh      =(const float*)d_in[12];
    const float* dec_b       =(const float*)d_in[13];
    const float* out_W1      =(const float*)d_in[14];
    const float* out_b1      =(const float*)d_in[15];
    const float* out_W2      =(const float*)d_in[16];
    const float* out_b2      =(const float*)d_in[17];
    float* out=(float*)d_out;

    float *pX0,*pZXe,*pZXd,*pH1,*pDO;
    int *pIin,*pItg;
    cudaGetSymbolAddress((void**)&pX0, g_X0);
    cudaGetSymbolAddress((void**)&pZXe,g_ZXe);
    cudaGetSymbolAddress((void**)&pZXd,g_ZXd);
    cudaGetSymbolAddress((void**)&pH1, g_H1);
    cudaGetSymbolAddress((void**)&pDO, g_dout);
    cudaGetSymbolAddress((void**)&pIin,g_idx_in);
    cudaGetSymbolAddress((void**)&pItg,g_idx_tg);

    const int RSMEM = 49152 * 4;  // 192KB dynamic smem
    cudaFuncSetAttribute(recurrent_k, cudaFuncAttributeMaxDynamicSharedMemorySize, RSMEM);

    // [0] prep + weight reorder (fused so recurrent_k is ncu launch index 5)
    prep_reorder_k<<<2048,256>>>(inputs,targets,enc_Wh,enc_Wx,dec_Wh,dec_Wx);
    // [1] enc: X0 = relu(gather(embed) @ enc_Wd + enc_bd)
    sgemm_k<<<dim3(4,64),256>>>(input_embed,enc_Wd,enc_bd,pX0,8192,512,64,pIin,0,1);
    // [2] enc: ZXe = X0 @ enc_Wx[0]   (layout [t][col][b])
    sgemm_k<<<dim3(16,64),256>>>(pX0,enc_Wx,nullptr,pZXe,8192,2048,512,nullptr,1,0);
    // [3] dec: X0 = relu(gather(dec_embed) @ dec_Wd + dec_bd)
    sgemm_k<<<dim3(4,64),256>>>(dec_embed,dec_Wd,dec_bd,pX0,8192,512,2048,pItg,0,1);
    // [4] dec: ZXd = X0 @ dec_Wx[0]
    sgemm_k<<<dim3(16,64),256>>>(pX0,dec_Wx,nullptr,pZXd,8192,2048,512,nullptr,1,0);
    // [5] recurrence (enc 128 + dec 128 steps)
    recurrent_k<<<128,128,RSMEM>>>(enc_b,dec_b);
    // [6] head: H1 = relu(dout @ out_W1 + out_b1)
    sgemm_k<<<dim3(16,64),256>>>(pDO,out_W1,out_b1,pH1,8192,2048,512,nullptr,0,1);
    // [7] head: out = relu(H1 @ out_W2 + out_b2), remapped to [B][T][P]
    sgemm_k<<<dim3(64,64),256>>>(pH1,out_W2,out_b2,out,8192,8192,2048,nullptr,2,1);
}